// round 7
// baseline (speedup 1.0000x reference)
#include <cuda_runtime.h>

#define H 128
#define C 8
#define NMAX 500000

// Scratch — 16B-aligned (float4 loads + red.v4 require it)
__device__ __align__(16) float g_deg[NMAX];              // 2 MB
__device__ __align__(16) float g_x  [(size_t)NMAX * C];  // 16 MB : raw h@W
__device__ __align__(16) float g_xs [(size_t)NMAX * C];  // 16 MB : x * dinv
__device__ __align__(16) float g_acc[(size_t)NMAX * C];  // 16 MB : accumulator
__device__ double g_loss;
__device__ int    g_idx64;   // 1 if index buffers are int64, 0 if int32

__device__ __forceinline__ long long ld_idx(const void* p, long long i, bool idx64) {
    if (idx64) return ((const long long*)p)[i];
    return (long long)((const int*)p)[i];
}

// ---------------------------------------------------------------------------
// Detect index dtype: int64 indices in [0,N) have zero upper words; int32
// data misread as int64 fuses random pairs into huge values.
// ---------------------------------------------------------------------------
__global__ void k_detect(const void* edge, long long n_elems, long long N) {
    if (threadIdx.x == 0 && blockIdx.x == 0) {
        const long long* p = (const long long*)edge;
        long long take = n_elems / 2 < 64 ? n_elems / 2 : 64;
        int ok = 1;
        for (long long i = 0; i < take; i++) {
            long long v = p[i];
            if (v < 0 || v >= N) { ok = 0; break; }
        }
        g_idx64 = ok;
    }
}

__global__ void k_init(int N) {
    int i = blockIdx.x * blockDim.x + threadIdx.x;
    int stride = gridDim.x * blockDim.x;
    for (int j = i; j < N; j += stride) g_deg[j] = 0.0f;
    if (i == 0) g_loss = 0.0;
}

// ---------------------------------------------------------------------------
// Fused: matmul role (2/3 blocks) + degree role (1/3 blocks), one launch.
// dst index j lives at element (E + j) of the edge base buffer.
// ---------------------------------------------------------------------------
__global__ void k_fused(const float* __restrict__ hid,
                        const float* __restrict__ Wm,
                        const void* __restrict__ edge,
                        int N, int E) {
    int bid  = blockIdx.x;
    int role = bid % 3;
    int trip = bid / 3;

    if (role < 2) {
        int vbid    = trip * 2 + role;
        int nvblk   = (gridDim.x / 3) * 2;
        int gwarp   = (vbid * blockDim.x + threadIdx.x) >> 5;
        int lane    = threadIdx.x & 31;
        int nwarps  = (nvblk * blockDim.x) >> 5;

        float w[4][C];
#pragma unroll
        for (int j = 0; j < 4; j++)
#pragma unroll
            for (int c = 0; c < C; c++)
                w[j][c] = __ldg(&Wm[(lane * 4 + j) * C + c]);

        for (int n = gwarp; n < N; n += nwarps) {
            float4 h = __ldcs(reinterpret_cast<const float4*>(hid + (size_t)n * H + lane * 4));
            float acc[C];
#pragma unroll
            for (int c = 0; c < C; c++)
                acc[c] = h.x * w[0][c] + h.y * w[1][c] + h.z * w[2][c] + h.w * w[3][c];
#pragma unroll
            for (int c = 0; c < C; c++) {
#pragma unroll
                for (int o = 16; o > 0; o >>= 1)
                    acc[c] += __shfl_xor_sync(0xffffffffu, acc[c], o);
            }
            if (lane < C)
                g_x[(size_t)n * C + lane] = acc[lane];
        }
    } else {
        bool idx64 = (g_idx64 != 0);
        int nvblk  = gridDim.x / 3;
        long long tid    = (long long)trip * blockDim.x + threadIdx.x;
        long long stride = (long long)nvblk * blockDim.x;
        for (long long i = tid; i < E; i += stride) {
            long long d = ld_idx(edge, (long long)E + i, idx64);   // dst half
            if ((unsigned long long)d < (unsigned long long)N)
                asm volatile("red.global.add.f32 [%0], %1;"
                             :: "l"(&g_deg[d]), "f"(1.0f) : "memory");
        }
    }
}

__global__ void k_scale(int N) {
    int i = blockIdx.x * blockDim.x + threadIdx.x;
    if (i >= N) return;
    float dinv = rsqrtf(g_deg[i] + 1.0f);
    const float4* xr = reinterpret_cast<const float4*>(g_x + (size_t)i * C);
    float4 a = xr[0], b = xr[1];
    a.x *= dinv; a.y *= dinv; a.z *= dinv; a.w *= dinv;
    b.x *= dinv; b.y *= dinv; b.z *= dinv; b.w *= dinv;
    float4* xs  = reinterpret_cast<float4*>(g_xs  + (size_t)i * C);
    float4* acc = reinterpret_cast<float4*>(g_acc + (size_t)i * C);
    xs[0] = a;  xs[1] = b;
    acc[0] = a; acc[1] = b;
}

__global__ void k_edges(const void* __restrict__ edge, int N, int E) {
    bool idx64 = (g_idx64 != 0);
    long long tid    = (long long)blockIdx.x * blockDim.x + threadIdx.x;
    long long stride = (long long)gridDim.x * blockDim.x;
    for (long long i = tid; i < E; i += stride) {
        long long s = ld_idx(edge, i, idx64);                    // src half
        long long d = ld_idx(edge, (long long)E + i, idx64);     // dst half
        if ((unsigned long long)s >= (unsigned long long)N) continue;
        if ((unsigned long long)d >= (unsigned long long)N) continue;
        const float4* xr = reinterpret_cast<const float4*>(g_xs + (size_t)s * C);
        float4 a = xr[0], b = xr[1];
        float* o = g_acc + (size_t)d * C;
        asm volatile("red.global.add.v4.f32 [%0], {%1,%2,%3,%4};"
                     :: "l"(o), "f"(a.x), "f"(a.y), "f"(a.z), "f"(a.w) : "memory");
        asm volatile("red.global.add.v4.f32 [%0], {%1,%2,%3,%4};"
                     :: "l"(o + 4), "f"(b.x), "f"(b.y), "f"(b.z), "f"(b.w) : "memory");
    }
}

__global__ void k_loss(const void* __restrict__ y,
                       const float* __restrict__ bias, int N) {
    bool idx64 = (g_idx64 != 0);
    int i = blockIdx.x * blockDim.x + threadIdx.x;
    float term = 0.0f;
    if (i < N) {
        float dinv = rsqrtf(g_deg[i] + 1.0f);
        const float4* ar = reinterpret_cast<const float4*>(g_acc + (size_t)i * C);
        float4 a0 = ar[0], a1 = ar[1];
        float v[C];
        v[0] = dinv * a0.x + __ldg(&bias[0]);
        v[1] = dinv * a0.y + __ldg(&bias[1]);
        v[2] = dinv * a0.z + __ldg(&bias[2]);
        v[3] = dinv * a0.w + __ldg(&bias[3]);
        v[4] = dinv * a1.x + __ldg(&bias[4]);
        v[5] = dinv * a1.y + __ldg(&bias[5]);
        v[6] = dinv * a1.z + __ldg(&bias[6]);
        v[7] = dinv * a1.w + __ldg(&bias[7]);
        float m = v[0];
#pragma unroll
        for (int c = 1; c < C; c++) m = fmaxf(m, v[c]);
        float s = 0.0f;
#pragma unroll
        for (int c = 0; c < C; c++) s += __expf(v[c] - m);
        int yc = (int)ld_idx(y, i, idx64);
        float picked = v[0];
#pragma unroll
        for (int c = 1; c < C; c++) picked = (yc == c) ? v[c] : picked;
        term = -(picked - m - __logf(s));
    }
#pragma unroll
    for (int o = 16; o > 0; o >>= 1)
        term += __shfl_xor_sync(0xffffffffu, term, o);
    __shared__ float sh[8];
    int warp = threadIdx.x >> 5;
    int lane = threadIdx.x & 31;
    if (lane == 0) sh[warp] = term;
    __syncthreads();
    if (warp == 0) {
        float v2 = (lane < (blockDim.x >> 5)) ? sh[lane] : 0.0f;
#pragma unroll
        for (int o = 4; o > 0; o >>= 1)
            v2 += __shfl_xor_sync(0xffffffffu, v2, o);
        if (lane == 0) atomicAdd(&g_loss, (double)v2);
    }
}

__global__ void k_final(float* out, int N) {
    out[0] = (float)(g_loss / (double)N);
}

extern "C" void kernel_launch(void* const* d_in, const int* in_sizes, int n_in,
                              void* d_out, int out_size) {
    // -------- size-based classification (no ordering assumption) --------
    const float* hiddens = nullptr; const float* Wm = nullptr; const float* bias = nullptr;
    const void*  edge = nullptr;    const void*  y = nullptr;
    long long hid_elems = 0, edge_elems = 0;
    for (int i = 0; i < n_in; i++) {
        long long s = in_sizes[i];
        if (s >= (1LL << 25))            { hiddens = (const float*)d_in[i]; hid_elems = s; }
        else if (s >= (1LL << 22))       { edge = d_in[i]; edge_elems = s; }
        else if (s >= 100000)            { y = d_in[i]; }
        else if (s >= 512 && s <= 4096)  { Wm = (const float*)d_in[i]; }
        else if (s <= 16)                { bias = (const float*)d_in[i]; }
        // ~2000-element q_edge_index ignored (forward loss doesn't use it)
    }
    int N = (int)(hid_elems / H);      // 500000
    int E = (int)(edge_elems / 2);     // 8000000

    k_detect<<<1, 32>>>(edge, edge_elems, N);
    k_init<<<592, 256>>>(N);
    k_fused<<<3552, 256>>>(hiddens, Wm, edge, N, E);
    k_scale<<<(N + 255) / 256, 256>>>(N);
    k_edges<<<2368, 256>>>(edge, N, E);
    k_loss<<<(N + 255) / 256, 256>>>(y, bias, N);
    k_final<<<1, 1>>>((float*)d_out, N);
}

// round 9
// speedup vs baseline: 1.0408x; 1.0408x over previous
#include <cuda_runtime.h>

#define H 128
#define C 8
#define NMAX 500000

// Scratch — 16B-aligned (float4 loads + red.v4 require it)
__device__ __align__(16) float g_deg[NMAX];              // 2 MB
__device__ __align__(16) float g_x  [(size_t)NMAX * C];  // 16 MB : raw h@W
__device__ __align__(16) float g_xs [(size_t)NMAX * C];  // 16 MB : x * dinv
__device__ __align__(16) float g_acc[(size_t)NMAX * C];  // 16 MB : accumulator
__device__ double g_loss;
__device__ int    g_idx64;   // 1 if index buffers are int64, 0 if int32

__device__ __forceinline__ long long ld_idx(const void* p, long long i, bool idx64) {
    if (idx64) return ((const long long*)p)[i];
    return (long long)((const int*)p)[i];
}

// ---------------------------------------------------------------------------
// K0: init — deg=0, loss=0, and (thread 0) detect index dtype.
// int64 indices in [0,N) have zero upper words; int32 data misread as int64
// fuses random pairs into huge values -> fails the range check.
// ---------------------------------------------------------------------------
__global__ void k_init(const void* edge, long long edge_elems, int N) {
    int i = blockIdx.x * blockDim.x + threadIdx.x;
    int stride = gridDim.x * blockDim.x;
    for (int j = i; j < N; j += stride) g_deg[j] = 0.0f;
    if (i == 0) {
        g_loss = 0.0;
        const long long* p = (const long long*)edge;
        long long take = edge_elems / 2 < 64 ? edge_elems / 2 : 64;
        int ok = 1;
        for (long long k = 0; k < take; k++) {
            long long v = p[k];
            if (v < 0 || v >= N) { ok = 0; break; }
        }
        g_idx64 = ok;
    }
}

// ---------------------------------------------------------------------------
// Fused: matmul role (2/3 blocks) + degree role (1/3 blocks), one launch.
// Degree role: ILP=4 with vectorized index loads.
// ---------------------------------------------------------------------------
__global__ void k_fused(const float* __restrict__ hid,
                        const float* __restrict__ Wm,
                        const void* __restrict__ edge,
                        int N, int E) {
    int bid  = blockIdx.x;
    int role = bid % 3;
    int trip = bid / 3;

    if (role < 2) {
        int vbid    = trip * 2 + role;
        int nvblk   = (gridDim.x / 3) * 2;
        int gwarp   = (vbid * blockDim.x + threadIdx.x) >> 5;
        int lane    = threadIdx.x & 31;
        int nwarps  = (nvblk * blockDim.x) >> 5;

        float w[4][C];
#pragma unroll
        for (int j = 0; j < 4; j++)
#pragma unroll
            for (int c = 0; c < C; c++)
                w[j][c] = __ldg(&Wm[(lane * 4 + j) * C + c]);

        for (int n = gwarp; n < N; n += nwarps) {
            float4 h = __ldcs(reinterpret_cast<const float4*>(hid + (size_t)n * H + lane * 4));
            float acc[C];
#pragma unroll
            for (int c = 0; c < C; c++)
                acc[c] = h.x * w[0][c] + h.y * w[1][c] + h.z * w[2][c] + h.w * w[3][c];
#pragma unroll
            for (int c = 0; c < C; c++) {
#pragma unroll
                for (int o = 16; o > 0; o >>= 1)
                    acc[c] += __shfl_xor_sync(0xffffffffu, acc[c], o);
            }
            if (lane < C)
                g_x[(size_t)n * C + lane] = acc[lane];
        }
    } else {
        // ---- degree role: ILP=4 quads over the dst half [E, 2E) ----
        bool idx64 = (g_idx64 != 0);
        int nvblk  = gridDim.x / 3;
        long long tid    = (long long)trip * blockDim.x + threadIdx.x;
        long long stride = (long long)nvblk * blockDim.x;
        long long nquads = E / 4;
        bool vec_ok = ((E & 3) == 0);

        for (long long q = tid; q < nquads; q += stride) {
            long long base = q * 4;
            long long d0, d1, d2, d3;
            if (!idx64 && vec_ok) {
                int4 dv = *reinterpret_cast<const int4*>((const int*)edge + E + base);
                d0 = dv.x; d1 = dv.y; d2 = dv.z; d3 = dv.w;
            } else if (idx64 && vec_ok) {
                const longlong2* p = reinterpret_cast<const longlong2*>((const long long*)edge + E + base);
                longlong2 v0 = p[0], v1 = p[1];
                d0 = v0.x; d1 = v0.y; d2 = v1.x; d3 = v1.y;
            } else {
                d0 = ld_idx(edge, (long long)E + base + 0, idx64);
                d1 = ld_idx(edge, (long long)E + base + 1, idx64);
                d2 = ld_idx(edge, (long long)E + base + 2, idx64);
                d3 = ld_idx(edge, (long long)E + base + 3, idx64);
            }
            if ((unsigned long long)d0 < (unsigned long long)N)
                asm volatile("red.global.add.f32 [%0], %1;" :: "l"(&g_deg[d0]), "f"(1.0f) : "memory");
            if ((unsigned long long)d1 < (unsigned long long)N)
                asm volatile("red.global.add.f32 [%0], %1;" :: "l"(&g_deg[d1]), "f"(1.0f) : "memory");
            if ((unsigned long long)d2 < (unsigned long long)N)
                asm volatile("red.global.add.f32 [%0], %1;" :: "l"(&g_deg[d2]), "f"(1.0f) : "memory");
            if ((unsigned long long)d3 < (unsigned long long)N)
                asm volatile("red.global.add.f32 [%0], %1;" :: "l"(&g_deg[d3]), "f"(1.0f) : "memory");
        }
        // tail
        if (tid == 0) {
            for (long long i = nquads * 4; i < E; i++) {
                long long d = ld_idx(edge, (long long)E + i, idx64);
                if ((unsigned long long)d < (unsigned long long)N)
                    asm volatile("red.global.add.f32 [%0], %1;" :: "l"(&g_deg[d]), "f"(1.0f) : "memory");
            }
        }
    }
}

__global__ void k_scale(int N) {
    int i = blockIdx.x * blockDim.x + threadIdx.x;
    if (i >= N) return;
    float dinv = rsqrtf(g_deg[i] + 1.0f);
    const float4* xr = reinterpret_cast<const float4*>(g_x + (size_t)i * C);
    float4 a = xr[0], b = xr[1];
    a.x *= dinv; a.y *= dinv; a.z *= dinv; a.w *= dinv;
    b.x *= dinv; b.y *= dinv; b.z *= dinv; b.w *= dinv;
    float4* xs  = reinterpret_cast<float4*>(g_xs  + (size_t)i * C);
    float4* acc = reinterpret_cast<float4*>(g_acc + (size_t)i * C);
    xs[0] = a;  xs[1] = b;
    acc[0] = a; acc[1] = b;
}

// ---------------------------------------------------------------------------
// Edge scatter — ILP=4: one thread owns 4 consecutive edges. Vector index
// loads, 4 batched 32B gathers (MLP=8), then 8 v4 REDs.
// ---------------------------------------------------------------------------
__global__ void k_edges(const void* __restrict__ edge, int N, int E) {
    bool idx64 = (g_idx64 != 0);
    long long q = (long long)blockIdx.x * blockDim.x + threadIdx.x;
    long long nquads = (E + 3) / 4;
    if (q >= nquads) return;
    long long base = q * 4;
    int cnt = (int)((base + 4 <= E) ? 4 : (E - base));

    long long s[4], d[4];
    if (cnt == 4 && !idx64 && ((E & 3) == 0)) {
        int4 sv = *reinterpret_cast<const int4*>((const int*)edge + base);
        int4 dv = *reinterpret_cast<const int4*>((const int*)edge + E + base);
        s[0] = sv.x; s[1] = sv.y; s[2] = sv.z; s[3] = sv.w;
        d[0] = dv.x; d[1] = dv.y; d[2] = dv.z; d[3] = dv.w;
    } else if (cnt == 4 && idx64 && ((E & 3) == 0)) {
        const longlong2* sp = reinterpret_cast<const longlong2*>((const long long*)edge + base);
        const longlong2* dp = reinterpret_cast<const longlong2*>((const long long*)edge + E + base);
        longlong2 s0 = sp[0], s1 = sp[1], d0v = dp[0], d1v = dp[1];
        s[0] = s0.x; s[1] = s0.y; s[2] = s1.x; s[3] = s1.y;
        d[0] = d0v.x; d[1] = d0v.y; d[2] = d1v.x; d[3] = d1v.y;
    } else {
#pragma unroll
        for (int j = 0; j < 4; j++) {
            if (j < cnt) {
                s[j] = ld_idx(edge, base + j, idx64);
                d[j] = ld_idx(edge, (long long)E + base + j, idx64);
            } else { s[j] = -1; d[j] = -1; }
        }
    }

    // batched gathers — independent loads, high MLP
    float4 a[4], b[4];
#pragma unroll
    for (int j = 0; j < 4; j++) {
        bool ok = (unsigned long long)s[j] < (unsigned long long)N;
        const float4* xr = reinterpret_cast<const float4*>(g_xs + (size_t)(ok ? s[j] : 0) * C);
        a[j] = xr[0];
        b[j] = xr[1];
        if (!ok) { a[j] = make_float4(0,0,0,0); b[j] = make_float4(0,0,0,0); }
    }

#pragma unroll
    for (int j = 0; j < 4; j++) {
        if ((unsigned long long)d[j] >= (unsigned long long)N) continue;
        if ((unsigned long long)s[j] >= (unsigned long long)N) continue;
        float* o = g_acc + (size_t)d[j] * C;
        asm volatile("red.global.add.v4.f32 [%0], {%1,%2,%3,%4};"
                     :: "l"(o), "f"(a[j].x), "f"(a[j].y), "f"(a[j].z), "f"(a[j].w) : "memory");
        asm volatile("red.global.add.v4.f32 [%0], {%1,%2,%3,%4};"
                     :: "l"(o + 4), "f"(b[j].x), "f"(b[j].y), "f"(b[j].z), "f"(b[j].w) : "memory");
    }
}

__global__ void k_loss(const void* __restrict__ y,
                       const float* __restrict__ bias, int N) {
    bool idx64 = (g_idx64 != 0);
    int i = blockIdx.x * blockDim.x + threadIdx.x;
    float term = 0.0f;
    if (i < N) {
        float dinv = rsqrtf(g_deg[i] + 1.0f);
        const float4* ar = reinterpret_cast<const float4*>(g_acc + (size_t)i * C);
        float4 a0 = ar[0], a1 = ar[1];
        float v[C];
        v[0] = dinv * a0.x + __ldg(&bias[0]);
        v[1] = dinv * a0.y + __ldg(&bias[1]);
        v[2] = dinv * a0.z + __ldg(&bias[2]);
        v[3] = dinv * a0.w + __ldg(&bias[3]);
        v[4] = dinv * a1.x + __ldg(&bias[4]);
        v[5] = dinv * a1.y + __ldg(&bias[5]);
        v[6] = dinv * a1.z + __ldg(&bias[6]);
        v[7] = dinv * a1.w + __ldg(&bias[7]);
        float m = v[0];
#pragma unroll
        for (int c = 1; c < C; c++) m = fmaxf(m, v[c]);
        float s = 0.0f;
#pragma unroll
        for (int c = 0; c < C; c++) s += __expf(v[c] - m);
        int yc = (int)ld_idx(y, i, idx64);
        float picked = v[0];
#pragma unroll
        for (int c = 1; c < C; c++) picked = (yc == c) ? v[c] : picked;
        term = -(picked - m - __logf(s));
    }
#pragma unroll
    for (int o = 16; o > 0; o >>= 1)
        term += __shfl_xor_sync(0xffffffffu, term, o);
    __shared__ float sh[8];
    int warp = threadIdx.x >> 5;
    int lane = threadIdx.x & 31;
    if (lane == 0) sh[warp] = term;
    __syncthreads();
    if (warp == 0) {
        float v2 = (lane < (blockDim.x >> 5)) ? sh[lane] : 0.0f;
#pragma unroll
        for (int o = 4; o > 0; o >>= 1)
            v2 += __shfl_xor_sync(0xffffffffu, v2, o);
        if (lane == 0) atomicAdd(&g_loss, (double)v2);
    }
}

__global__ void k_final(float* out, int N) {
    out[0] = (float)(g_loss / (double)N);
}

extern "C" void kernel_launch(void* const* d_in, const int* in_sizes, int n_in,
                              void* d_out, int out_size) {
    // -------- size-based classification (no ordering assumption) --------
    const float* hiddens = nullptr; const float* Wm = nullptr; const float* bias = nullptr;
    const void*  edge = nullptr;    const void*  y = nullptr;
    long long hid_elems = 0, edge_elems = 0;
    for (int i = 0; i < n_in; i++) {
        long long s = in_sizes[i];
        if (s >= (1LL << 25))            { hiddens = (const float*)d_in[i]; hid_elems = s; }
        else if (s >= (1LL << 22))       { edge = d_in[i]; edge_elems = s; }
        else if (s >= 100000)            { y = d_in[i]; }
        else if (s >= 512 && s <= 4096)  { Wm = (const float*)d_in[i]; }
        else if (s <= 16)                { bias = (const float*)d_in[i]; }
        // ~2000-element q_edge_index ignored (forward loss doesn't use it)
    }
    int N = (int)(hid_elems / H);      // 500000
    int E = (int)(edge_elems / 2);     // 8000000

    k_init<<<592, 256>>>(edge, edge_elems, N);
    k_fused<<<3552, 256>>>(hiddens, Wm, edge, N, E);
    k_scale<<<(N + 255) / 256, 256>>>(N);
    long long nquads = ((long long)E + 3) / 4;
    k_edges<<<(int)((nquads + 255) / 256), 256>>>(edge, N, E);
    k_loss<<<(N + 255) / 256, 256>>>(y, bias, N);
    k_final<<<1, 1>>>((float*)d_out, N);
}